// round 5
// baseline (speedup 1.0000x reference)
#include <cuda_runtime.h>
#include <cstdint>

// Problem constants
#define B_ROWS 4096
#define NDOM 8
#define D0 1024
#define D1 1024
#define D2 512
#define D3 256
#define MAXTILES 72          // sum over domains of ceil(len/64) <= 64 + 8

// ---------------- device scratch ----------------
__device__ int   g_perm[B_ROWS];
__device__ int   g_off[NDOM + 1];
__device__ int   g_tile_d[MAXTILES];
__device__ int   g_tile_m[MAXTILES];
__device__ int   g_ntiles;
__device__ float g_h1[B_ROWS * D1];
__device__ float g_h2[B_ROWS * D2];

__device__ __forceinline__ float tf32r(float x) {
    uint32_t u;
    asm("cvt.rna.tf32.f32 %0, %1;" : "=r"(u) : "f"(x));
    return __uint_as_float(u);
}

#define MMA_TF32(d, a0, a1, a2, a3, b0, b1)                                   \
    asm volatile(                                                             \
        "mma.sync.aligned.m16n8k8.row.col.f32.tf32.tf32.f32 "                 \
        "{%0,%1,%2,%3}, {%4,%5,%6,%7}, {%8,%9}, {%0,%1,%2,%3};"               \
        : "+f"((d)[0]), "+f"((d)[1]), "+f"((d)[2]), "+f"((d)[3])              \
        : "r"(a0), "r"(a1), "r"(a2), "r"(a3), "r"(b0), "r"(b1))

// ---------------- permutation + tile list ----------------
__global__ void build_perm(const int* __restrict__ ind) {
    __shared__ int cnt[NDOM];
    __shared__ int cur[NDOM];
    int t = threadIdx.x;
    if (t < NDOM) cnt[t] = 0;
    __syncthreads();
    for (int i = t; i < B_ROWS; i += blockDim.x) atomicAdd(&cnt[ind[i]], 1);
    __syncthreads();
    if (t == 0) {
        int s = 0;
        for (int d = 0; d < NDOM; d++) { g_off[d] = s; cur[d] = s; s += cnt[d]; }
        g_off[NDOM] = s;
        int nt = 0;
        for (int d = 0; d < NDOM; d++) {
            int len = g_off[d + 1] - g_off[d];
            for (int m0 = 0; m0 < len; m0 += 64) {
                g_tile_d[nt] = d; g_tile_m[nt] = m0; nt++;
            }
        }
        g_ntiles = nt;
    }
    __syncthreads();
    for (int i = t; i < B_ROWS; i += blockDim.x) {
        int d = ind[i];
        int p = atomicAdd(&cur[d], 1);
        g_perm[p] = i;
    }
}

// ---------------- smem layout (floats) ----------------
// A fragments, MMA-permuted: [buf][split][mtile 0..3][lane 0..31][20]
#define AF_SZ (2 * 2 * 4 * 32 * 20)       // 10240 floats
// B tiles: [buf][split][k 0..31][BPAD], value = weff(k, n0+n)
#define BPAD 132
#define B_SZ (2 * 2 * 32 * BPAD)          // 16896 floats
#define SM_B       AF_SZ
#define SM_ROWIDX  (AF_SZ + B_SZ)
#define SM_BIAS    (SM_ROWIDX + 64)
#define GEMM_SMEM  ((SM_BIAS + 128) * 4)  // ~107 KB -> 2 CTAs/SM

__device__ __forceinline__ int af_off(int buf, int split, int mtile) {
    return ((buf * 2 + split) * 4 + mtile) * 640;   // 32*20
}
__device__ __forceinline__ int b_off(int buf, int split) {
    return SM_B + (buf * 2 + split) * (32 * BPAD);
}

// ---------------- 3xTF32 mma.sync grouped GEMM, fused weight build ----------
// Block tile M=64, N=128, K-chunk 32, double-buffered. 8 warps (2M x 4N),
// warp tile 32x32. 2 CTAs/SM.
template <int LAYER>
__global__ __launch_bounds__(256, 2)
void gemm_mma(const float* __restrict__ xin, const float* __restrict__ sk,
              const float* __restrict__ dkk, const float* __restrict__ sb,
              const float* __restrict__ db, float* __restrict__ outp) {
    constexpr int K = (LAYER == 0) ? D0 : (LAYER == 1) ? D1 : D2;
    constexpr int N = (LAYER == 0) ? D1 : (LAYER == 1) ? D2 : D3;
    constexpr int NCH = K / 32;

    const int tyb = blockIdx.y;
    if (tyb >= g_ntiles) return;
    const int d   = g_tile_d[tyb];
    const int m0  = g_tile_m[tyb];
    const int off = g_off[d];
    const int len = g_off[d + 1] - off;
    const int n0  = blockIdx.x * 128;

    extern __shared__ float smf[];
    int*   rowIdx = (int*)(smf + SM_ROWIDX);
    float* biasS  = smf + SM_BIAS;

    const int tid  = threadIdx.x;
    const int lane = tid & 31;
    const int w    = tid >> 5;
    const int mw   = w >> 2;        // 0..1 -> M offset mw*32
    const int nw   = w & 3;         // 0..3 -> N offset nw*32
    const int grp  = lane >> 2;
    const int tig  = lane & 3;

    if (tid < 64) {
        int r = m0 + tid;
        int row = -1;
        if (r < len) row = (LAYER == 0) ? g_perm[off + r] : (off + r);
        rowIdx[tid] = row;
    }
    if (tid >= 128 && tid < 160) {
        int q = tid - 128;
        float4 a = *(const float4*)(sb + n0 + q * 4);
        float4 b = *(const float4*)(db + (size_t)d * N + n0 + q * 4);
        a.x += b.x; a.y += b.y; a.z += b.z; a.w += b.w;
        *(float4*)(biasS + q * 4) = a;
    }
    __syncthreads();

    const float* Ap  = (LAYER == 0) ? xin : (LAYER == 1) ? g_h1 : g_h2;
    float*       Cp  = (LAYER == 0) ? g_h1 : (LAYER == 1) ? g_h2 : outp;
    const float* dkd = dkk + (size_t)d * K * N;

    float acc[2][4][4];
#pragma unroll
    for (int i = 0; i < 2; i++)
#pragma unroll
        for (int j = 0; j < 4; j++)
#pragma unroll
            for (int q = 0; q < 4; q++) acc[i][j][q] = 0.f;

    // loader coords: A rows ldr+32i (i<2), k cols fq*4..; B row k=ldr, cols (fq+8i)*4
    const int ldr = tid >> 3;
    const int fq  = tid & 7;
    int rws[2];
#pragma unroll
    for (int i = 0; i < 2; i++) rws[i] = rowIdx[ldr + 32 * i];

    float4 avA[2], avW[4];

#define LOADC(c)                                                              \
    {                                                                         \
        const int k0 = (c) * 32;                                              \
        _Pragma("unroll")                                                     \
        for (int i = 0; i < 2; i++) {                                         \
            int rr = rws[i];                                                  \
            avA[i] = (rr >= 0)                                                \
                ? *(const float4*)(Ap + (size_t)rr * K + k0 + fq * 4)         \
                : make_float4(0.f, 0.f, 0.f, 0.f);                            \
        }                                                                     \
        _Pragma("unroll")                                                     \
        for (int i = 0; i < 4; i++) {                                         \
            int co = n0 + (fq + 8 * i) * 4;                                   \
            float4 s = *(const float4*)(sk  + (size_t)(k0 + ldr) * N + co);   \
            float4 t = *(const float4*)(dkd + (size_t)(k0 + ldr) * N + co);   \
            avW[i].x = s.x * t.x; avW[i].y = s.y * t.y;                       \
            avW[i].z = s.z * t.z; avW[i].w = s.w * t.w;                       \
        }                                                                     \
    }

#define STOREC(c)                                                             \
    {                                                                         \
        const int buf = (c) & 1;                                              \
        const int ks  = fq >> 1;                                              \
        const int kh2 = (fq & 1) * 2;                                         \
        _Pragma("unroll")                                                     \
        for (int i = 0; i < 2; i++) {                                         \
            int row = ldr + 32 * i;                                           \
            int mt  = row >> 4;                                               \
            int l0  = (row & 7) * 4;                                          \
            int ai  = ((row & 15) >= 8 ? 1 : 0) + kh2;                        \
            float* pb = smf + af_off(buf, 0, mt) + ks * 4 + ai;               \
            float* ps = smf + af_off(buf, 1, mt) + ks * 4 + ai;               \
            float4 v = avA[i];                                                \
            float bx = tf32r(v.x), by = tf32r(v.y);                           \
            float bz = tf32r(v.z), bw = tf32r(v.w);                           \
            pb[(l0 + 0) * 20] = bx; ps[(l0 + 0) * 20] = tf32r(v.x - bx);      \
            pb[(l0 + 1) * 20] = by; ps[(l0 + 1) * 20] = tf32r(v.y - by);      \
            pb[(l0 + 2) * 20] = bz; ps[(l0 + 2) * 20] = tf32r(v.z - bz);      \
            pb[(l0 + 3) * 20] = bw; ps[(l0 + 3) * 20] = tf32r(v.w - bw);      \
        }                                                                     \
        _Pragma("unroll")                                                     \
        for (int i = 0; i < 4; i++) {                                         \
            float4 wv = avW[i];                                               \
            float4 wb, ws;                                                    \
            wb.x = tf32r(wv.x); ws.x = tf32r(wv.x - wb.x);                    \
            wb.y = tf32r(wv.y); ws.y = tf32r(wv.y - wb.y);                    \
            wb.z = tf32r(wv.z); ws.z = tf32r(wv.z - wb.z);                    \
            wb.w = tf32r(wv.w); ws.w = tf32r(wv.w - wb.w);                    \
            int o = ldr * BPAD + (fq + 8 * i) * 4;                            \
            *(float4*)(smf + b_off(buf, 0) + o) = wb;                         \
            *(float4*)(smf + b_off(buf, 1) + o) = ws;                         \
        }                                                                     \
    }

    LOADC(0);
    STOREC(0);

    for (int c = 0; c < NCH; c++) {
        const int buf = c & 1;
        __syncthreads();
        if (c + 1 < NCH) LOADC(c + 1);

        const float* afb = smf + af_off(buf, 0, mw * 2) + lane * 20;
        const float* afs = smf + af_off(buf, 1, mw * 2) + lane * 20;
        const float* bpb = smf + b_off(buf, 0);
        const float* bps = smf + b_off(buf, 1);
#pragma unroll
        for (int ks = 0; ks < 4; ks++) {
            uint4 fab[2], fas[2];
#pragma unroll
            for (int mt = 0; mt < 2; mt++) {
                fab[mt] = *(const uint4*)(afb + mt * 640 + ks * 4);
                fas[mt] = *(const uint4*)(afs + mt * 640 + ks * 4);
            }
            const int kc = ks * 8 + tig;
#pragma unroll
            for (int nt = 0; nt < 4; nt++) {
                int ncol = nw * 32 + nt * 8 + grp;
                uint32_t bb0 = __float_as_uint(bpb[kc * BPAD + ncol]);
                uint32_t bb1 = __float_as_uint(bpb[(kc + 4) * BPAD + ncol]);
                uint32_t bs0 = __float_as_uint(bps[kc * BPAD + ncol]);
                uint32_t bs1 = __float_as_uint(bps[(kc + 4) * BPAD + ncol]);
#pragma unroll
                for (int mt = 0; mt < 2; mt++) {
                    MMA_TF32(acc[mt][nt], fab[mt].x, fab[mt].y, fab[mt].z, fab[mt].w, bb0, bb1);
                    MMA_TF32(acc[mt][nt], fab[mt].x, fab[mt].y, fab[mt].z, fab[mt].w, bs0, bs1);
                    MMA_TF32(acc[mt][nt], fas[mt].x, fas[mt].y, fas[mt].z, fas[mt].w, bb0, bb1);
                }
            }
        }
        if (c + 1 < NCH) STOREC(c + 1);
    }

    // ---------------- epilogue: bias + relu + (scatter) store ----------------
#pragma unroll
    for (int mt = 0; mt < 2; mt++) {
#pragma unroll
        for (int half = 0; half < 2; half++) {
            int mrow = mw * 32 + mt * 16 + grp + half * 8;
            int r = m0 + mrow;
            if (r < len) {
                int orow = (LAYER == 2) ? g_perm[off + r] : (off + r);
                float* crow = Cp + (size_t)orow * N + n0;
#pragma unroll
                for (int nt = 0; nt < 4; nt++) {
                    int col = nw * 32 + nt * 8 + 2 * tig;
                    float2 o;
                    o.x = fmaxf(acc[mt][nt][half * 2 + 0] + biasS[col], 0.f);
                    o.y = fmaxf(acc[mt][nt][half * 2 + 1] + biasS[col + 1], 0.f);
                    *(float2*)(crow + col) = o;
                }
            }
        }
    }
}

// ---------------- launch ----------------
extern "C" void kernel_launch(void* const* d_in, const int* in_sizes, int n_in,
                              void* d_out, int out_size) {
    const float* x   = (const float*)d_in[0];
    const int*   ind = (const int*)  d_in[1];
    const float* sk0 = (const float*)d_in[2];
    const float* sb0 = (const float*)d_in[3];
    const float* dk0 = (const float*)d_in[4];
    const float* db0 = (const float*)d_in[5];
    const float* sk1 = (const float*)d_in[6];
    const float* sb1 = (const float*)d_in[7];
    const float* dk1 = (const float*)d_in[8];
    const float* db1 = (const float*)d_in[9];
    const float* sk2 = (const float*)d_in[10];
    const float* sb2 = (const float*)d_in[11];
    const float* dk2 = (const float*)d_in[12];
    const float* db2 = (const float*)d_in[13];
    float* out = (float*)d_out;

    cudaFuncSetAttribute(gemm_mma<0>, cudaFuncAttributeMaxDynamicSharedMemorySize, GEMM_SMEM);
    cudaFuncSetAttribute(gemm_mma<1>, cudaFuncAttributeMaxDynamicSharedMemorySize, GEMM_SMEM);
    cudaFuncSetAttribute(gemm_mma<2>, cudaFuncAttributeMaxDynamicSharedMemorySize, GEMM_SMEM);

    build_perm<<<1, 256>>>(ind);

    gemm_mma<0><<<dim3(D1 / 128, MAXTILES), 256, GEMM_SMEM>>>(x, sk0, dk0, sb0, db0, nullptr);
    gemm_mma<1><<<dim3(D2 / 128, MAXTILES), 256, GEMM_SMEM>>>(nullptr, sk1, dk1, sb1, db1, nullptr);
    gemm_mma<2><<<dim3(D3 / 128, MAXTILES), 256, GEMM_SMEM>>>(nullptr, sk2, dk2, sb2, db2, out);
}

// round 6
// speedup vs baseline: 1.0106x; 1.0106x over previous
#include <cuda_runtime.h>
#include <cstdint>

// Problem constants
#define B_ROWS 4096
#define NDOM 8
#define D0 1024
#define D1 1024
#define D2 512
#define D3 256
#define MAXTILES 40

// ---------------- device scratch ----------------
__device__ int   g_perm[B_ROWS];
__device__ int   g_off[NDOM + 1];
__device__ int   g_tile_d[MAXTILES];
__device__ int   g_tile_m[MAXTILES];
__device__ int   g_ntiles;
__device__ float g_h1[B_ROWS * D1];
__device__ float g_h2[B_ROWS * D2];

__device__ __forceinline__ float tf32r(float x) {
    uint32_t u;
    asm("cvt.rna.tf32.f32 %0, %1;" : "=r"(u) : "f"(x));
    return __uint_as_float(u);
}

#define MMA_TF32(d, a0, a1, a2, a3, b0, b1)                                   \
    asm volatile(                                                             \
        "mma.sync.aligned.m16n8k8.row.col.f32.tf32.tf32.f32 "                 \
        "{%0,%1,%2,%3}, {%4,%5,%6,%7}, {%8,%9}, {%0,%1,%2,%3};"               \
        : "+f"((d)[0]), "+f"((d)[1]), "+f"((d)[2]), "+f"((d)[3])              \
        : "r"(a0), "r"(a1), "r"(a2), "r"(a3), "r"(b0), "r"(b1))

// ---------------- permutation + tile list ----------------
__global__ void build_perm(const int* __restrict__ ind) {
    __shared__ int cnt[NDOM];
    __shared__ int cur[NDOM];
    int t = threadIdx.x;
    if (t < NDOM) cnt[t] = 0;
    __syncthreads();
    for (int i = t; i < B_ROWS; i += blockDim.x) atomicAdd(&cnt[ind[i]], 1);
    __syncthreads();
    if (t == 0) {
        int s = 0;
        for (int d = 0; d < NDOM; d++) { g_off[d] = s; cur[d] = s; s += cnt[d]; }
        g_off[NDOM] = s;
        int nt = 0;
        for (int d = 0; d < NDOM; d++) {
            int len = g_off[d + 1] - g_off[d];
            for (int m0 = 0; m0 < len; m0 += 128) {
                g_tile_d[nt] = d; g_tile_m[nt] = m0; nt++;
            }
        }
        g_ntiles = nt;
    }
    __syncthreads();
    for (int i = t; i < B_ROWS; i += blockDim.x) {
        int d = ind[i];
        int p = atomicAdd(&cur[d], 1);
        g_perm[p] = i;
    }
}

// ---------------- smem layout (floats) ----------------
// A fragments, MMA-permuted: [buf][split][mtile 0..7][lane 0..31][20]
#define AF_SZ (2 * 2 * 8 * 32 * 20)       // 20480 floats
// B tiles: [buf][split][k 0..31][BPAD], value = weff(k, n0+n)
#define BPAD 132
#define B_SZ (2 * 2 * 32 * BPAD)          // 16896 floats
#define SM_B       AF_SZ
#define SM_ROWIDX  (AF_SZ + B_SZ)
#define SM_BIAS    (SM_ROWIDX + 128)
#define GEMM_SMEM  ((SM_BIAS + 128) * 4)  // ~150.5 KB

__device__ __forceinline__ int af_off(int buf, int split, int mtile) {
    return ((buf * 2 + split) * 8 + mtile) * 640;   // 32*20
}
__device__ __forceinline__ int b_off(int buf, int split) {
    return SM_B + (buf * 2 + split) * (32 * BPAD);
}

// ---------------- 3xTF32 mma.sync grouped GEMM, fused weight build ----------
// Block tile M=128, N=128, K-chunk 32, double-buffered. 8 warps (2M x 4N).
// Inner loop: three split-major passes of 16 independent MMAs (no RAW chains).
template <int LAYER>
__global__ __launch_bounds__(256, 1)
void gemm_mma(const float* __restrict__ xin, const float* __restrict__ sk,
              const float* __restrict__ dkk, const float* __restrict__ sb,
              const float* __restrict__ db, float* __restrict__ outp) {
    constexpr int K = (LAYER == 0) ? D0 : (LAYER == 1) ? D1 : D2;
    constexpr int N = (LAYER == 0) ? D1 : (LAYER == 1) ? D2 : D3;
    constexpr int NCH = K / 32;

    const int tyb = blockIdx.y;
    if (tyb >= g_ntiles) return;
    const int d   = g_tile_d[tyb];
    const int m0  = g_tile_m[tyb];
    const int off = g_off[d];
    const int len = g_off[d + 1] - off;
    const int n0  = blockIdx.x * 128;

    extern __shared__ float smf[];
    int*   rowIdx = (int*)(smf + SM_ROWIDX);
    float* biasS  = smf + SM_BIAS;

    const int tid  = threadIdx.x;
    const int lane = tid & 31;
    const int w    = tid >> 5;
    const int mw   = w >> 2;
    const int nw   = w & 3;
    const int grp  = lane >> 2;
    const int tig  = lane & 3;

    if (tid < 128) {
        int r = m0 + tid;
        int row = -1;
        if (r < len) row = (LAYER == 0) ? g_perm[off + r] : (off + r);
        rowIdx[tid] = row;
    }
    if (tid >= 128 && tid < 160) {
        int q = tid - 128;
        float4 a = *(const float4*)(sb + n0 + q * 4);
        float4 b = *(const float4*)(db + (size_t)d * N + n0 + q * 4);
        a.x += b.x; a.y += b.y; a.z += b.z; a.w += b.w;
        *(float4*)(biasS + q * 4) = a;
    }
    __syncthreads();

    const float* Ap  = (LAYER == 0) ? xin : (LAYER == 1) ? g_h1 : g_h2;
    float*       Cp  = (LAYER == 0) ? g_h1 : (LAYER == 1) ? g_h2 : outp;
    const float* dkd = dkk + (size_t)d * K * N;

    float acc[4][4][4];
#pragma unroll
    for (int i = 0; i < 4; i++)
#pragma unroll
        for (int j = 0; j < 4; j++)
#pragma unroll
            for (int q = 0; q < 4; q++) acc[i][j][q] = 0.f;

    const int ldr = tid >> 3;
    const int fq  = tid & 7;
    int rws[4];
#pragma unroll
    for (int i = 0; i < 4; i++) rws[i] = rowIdx[ldr + 32 * i];

    float4 avA[4], avW[4];

#define LOADC(c)                                                              \
    {                                                                         \
        const int k0 = (c) * 32;                                              \
        _Pragma("unroll")                                                     \
        for (int i = 0; i < 4; i++) {                                         \
            int rr = rws[i];                                                  \
            avA[i] = (rr >= 0)                                                \
                ? *(const float4*)(Ap + (size_t)rr * K + k0 + fq * 4)         \
                : make_float4(0.f, 0.f, 0.f, 0.f);                            \
        }                                                                     \
        _Pragma("unroll")                                                     \
        for (int i = 0; i < 4; i++) {                                         \
            int co = n0 + (fq + 8 * i) * 4;                                   \
            float4 s = *(const float4*)(sk  + (size_t)(k0 + ldr) * N + co);   \
            float4 t = *(const float4*)(dkd + (size_t)(k0 + ldr) * N + co);   \
            avW[i].x = s.x * t.x; avW[i].y = s.y * t.y;                       \
            avW[i].z = s.z * t.z; avW[i].w = s.w * t.w;                       \
        }                                                                     \
    }

#define STOREC(c)                                                             \
    {                                                                         \
        const int buf = (c) & 1;                                              \
        const int ks  = fq >> 1;                                              \
        const int kh2 = (fq & 1) * 2;                                         \
        _Pragma("unroll")                                                     \
        for (int i = 0; i < 4; i++) {                                         \
            int row = ldr + 32 * i;                                           \
            int mt  = row >> 4;                                               \
            int l0  = (row & 7) * 4;                                          \
            int ai  = ((row & 15) >= 8 ? 1 : 0) + kh2;                        \
            float* pb = smf + af_off(buf, 0, mt) + ks * 4 + ai;               \
            float* ps = smf + af_off(buf, 1, mt) + ks * 4 + ai;               \
            float4 v = avA[i];                                                \
            float bx = tf32r(v.x), by = tf32r(v.y);                           \
            float bz = tf32r(v.z), bw = tf32r(v.w);                           \
            pb[(l0 + 0) * 20] = bx; ps[(l0 + 0) * 20] = tf32r(v.x - bx);      \
            pb[(l0 + 1) * 20] = by; ps[(l0 + 1) * 20] = tf32r(v.y - by);      \
            pb[(l0 + 2) * 20] = bz; ps[(l0 + 2) * 20] = tf32r(v.z - bz);      \
            pb[(l0 + 3) * 20] = bw; ps[(l0 + 3) * 20] = tf32r(v.w - bw);      \
        }                                                                     \
        _Pragma("unroll")                                                     \
        for (int i = 0; i < 4; i++) {                                         \
            float4 wv = avW[i];                                               \
            float4 wb, ws;                                                    \
            wb.x = tf32r(wv.x); ws.x = tf32r(wv.x - wb.x);                    \
            wb.y = tf32r(wv.y); ws.y = tf32r(wv.y - wb.y);                    \
            wb.z = tf32r(wv.z); ws.z = tf32r(wv.z - wb.z);                    \
            wb.w = tf32r(wv.w); ws.w = tf32r(wv.w - wb.w);                    \
            int o = ldr * BPAD + (fq + 8 * i) * 4;                            \
            *(float4*)(smf + b_off(buf, 0) + o) = wb;                         \
            *(float4*)(smf + b_off(buf, 1) + o) = ws;                         \
        }                                                                     \
    }

    LOADC(0);
    STOREC(0);

    for (int c = 0; c < NCH; c++) {
        const int buf = c & 1;
        __syncthreads();
        if (c + 1 < NCH) LOADC(c + 1);

        const float* afb = smf + af_off(buf, 0, mw * 4) + lane * 20;
        const float* afs = smf + af_off(buf, 1, mw * 4) + lane * 20;
        const float* bpb = smf + b_off(buf, 0);
        const float* bps = smf + b_off(buf, 1);
#pragma unroll
        for (int ks = 0; ks < 4; ks++) {
            const int kc = ks * 8 + tig;
            uint4 fab[4], fas[4];
#pragma unroll
            for (int mt = 0; mt < 4; mt++) {
                fab[mt] = *(const uint4*)(afb + mt * 640 + ks * 4);
                fas[mt] = *(const uint4*)(afs + mt * 640 + ks * 4);
            }
            uint32_t bb[4][2], bs[4][2];
#pragma unroll
            for (int nt = 0; nt < 4; nt++) {
                int ncol = nw * 32 + nt * 8 + grp;
                bb[nt][0] = __float_as_uint(bpb[kc * BPAD + ncol]);
                bb[nt][1] = __float_as_uint(bpb[(kc + 4) * BPAD + ncol]);
                bs[nt][0] = __float_as_uint(bps[kc * BPAD + ncol]);
                bs[nt][1] = __float_as_uint(bps[(kc + 4) * BPAD + ncol]);
            }
            // pass 1: Ab x Bb — 16 independent MMAs
#pragma unroll
            for (int nt = 0; nt < 4; nt++)
#pragma unroll
                for (int mt = 0; mt < 4; mt++)
                    MMA_TF32(acc[mt][nt], fab[mt].x, fab[mt].y, fab[mt].z, fab[mt].w,
                             bb[nt][0], bb[nt][1]);
            // pass 2: Ab x Bs
#pragma unroll
            for (int nt = 0; nt < 4; nt++)
#pragma unroll
                for (int mt = 0; mt < 4; mt++)
                    MMA_TF32(acc[mt][nt], fab[mt].x, fab[mt].y, fab[mt].z, fab[mt].w,
                             bs[nt][0], bs[nt][1]);
            // pass 3: As x Bb
#pragma unroll
            for (int nt = 0; nt < 4; nt++)
#pragma unroll
                for (int mt = 0; mt < 4; mt++)
                    MMA_TF32(acc[mt][nt], fas[mt].x, fas[mt].y, fas[mt].z, fas[mt].w,
                             bb[nt][0], bb[nt][1]);
        }
        if (c + 1 < NCH) STOREC(c + 1);
    }

    // ---------------- epilogue: bias + relu + (scatter) store ----------------
#pragma unroll
    for (int mt = 0; mt < 4; mt++) {
#pragma unroll
        for (int half = 0; half < 2; half++) {
            int mrow = mw * 64 + mt * 16 + grp + half * 8;
            int r = m0 + mrow;
            if (r < len) {
                int orow = (LAYER == 2) ? g_perm[off + r] : (off + r);
                float* crow = Cp + (size_t)orow * N + n0;
#pragma unroll
                for (int nt = 0; nt < 4; nt++) {
                    int col = nw * 32 + nt * 8 + 2 * tig;
                    float2 o;
                    o.x = fmaxf(acc[mt][nt][half * 2 + 0] + biasS[col], 0.f);
                    o.y = fmaxf(acc[mt][nt][half * 2 + 1] + biasS[col + 1], 0.f);
                    *(float2*)(crow + col) = o;
                }
            }
        }
    }
}

// ---------------- launch ----------------
extern "C" void kernel_launch(void* const* d_in, const int* in_sizes, int n_in,
                              void* d_out, int out_size) {
    const float* x   = (const float*)d_in[0];
    const int*   ind = (const int*)  d_in[1];
    const float* sk0 = (const float*)d_in[2];
    const float* sb0 = (const float*)d_in[3];
    const float* dk0 = (const float*)d_in[4];
    const float* db0 = (const float*)d_in[5];
    const float* sk1 = (const float*)d_in[6];
    const float* sb1 = (const float*)d_in[7];
    const float* dk1 = (const float*)d_in[8];
    const float* db1 = (const float*)d_in[9];
    const float* sk2 = (const float*)d_in[10];
    const float* sb2 = (const float*)d_in[11];
    const float* dk2 = (const float*)d_in[12];
    const float* db2 = (const float*)d_in[13];
    float* out = (float*)d_out;

    cudaFuncSetAttribute(gemm_mma<0>, cudaFuncAttributeMaxDynamicSharedMemorySize, GEMM_SMEM);
    cudaFuncSetAttribute(gemm_mma<1>, cudaFuncAttributeMaxDynamicSharedMemorySize, GEMM_SMEM);
    cudaFuncSetAttribute(gemm_mma<2>, cudaFuncAttributeMaxDynamicSharedMemorySize, GEMM_SMEM);

    build_perm<<<1, 256>>>(ind);

    gemm_mma<0><<<dim3(D1 / 128, MAXTILES), 256, GEMM_SMEM>>>(x, sk0, dk0, sb0, db0, nullptr);
    gemm_mma<1><<<dim3(D2 / 128, MAXTILES), 256, GEMM_SMEM>>>(nullptr, sk1, dk1, sb1, db1, nullptr);
    gemm_mma<2><<<dim3(D3 / 128, MAXTILES), 256, GEMM_SMEM>>>(nullptr, sk2, dk2, sb2, db2, out);
}

// round 7
// speedup vs baseline: 1.0255x; 1.0147x over previous
#include <cuda_runtime.h>
#include <cstdint>

// Problem constants
#define B_ROWS 4096
#define NDOM 8
#define D0 1024
#define D1 1024
#define D2 512
#define D3 256
#define MAXTILES 40
#define THREADS 512

// ---------------- device scratch ----------------
__device__ int   g_perm[B_ROWS];
__device__ int   g_off[NDOM + 1];
__device__ int   g_tile_d[MAXTILES];
__device__ int   g_tile_m[MAXTILES];
__device__ int   g_ntiles;
__device__ float g_h1[B_ROWS * D1];
__device__ float g_h2[B_ROWS * D2];

__device__ __forceinline__ float tf32r(float x) {
    uint32_t u;
    asm("cvt.rna.tf32.f32 %0, %1;" : "=r"(u) : "f"(x));
    return __uint_as_float(u);
}

#define MMA_TF32(d, a0, a1, a2, a3, b0, b1)                                   \
    asm volatile(                                                             \
        "mma.sync.aligned.m16n8k8.row.col.f32.tf32.tf32.f32 "                 \
        "{%0,%1,%2,%3}, {%4,%5,%6,%7}, {%8,%9}, {%0,%1,%2,%3};"               \
        : "+f"((d)[0]), "+f"((d)[1]), "+f"((d)[2]), "+f"((d)[3])              \
        : "r"(a0), "r"(a1), "r"(a2), "r"(a3), "r"(b0), "r"(b1))

// ---------------- permutation + tile list ----------------
__global__ void build_perm(const int* __restrict__ ind) {
    __shared__ int cnt[NDOM];
    __shared__ int cur[NDOM];
    int t = threadIdx.x;
    if (t < NDOM) cnt[t] = 0;
    __syncthreads();
    for (int i = t; i < B_ROWS; i += blockDim.x) atomicAdd(&cnt[ind[i]], 1);
    __syncthreads();
    if (t == 0) {
        int s = 0;
        for (int d = 0; d < NDOM; d++) { g_off[d] = s; cur[d] = s; s += cnt[d]; }
        g_off[NDOM] = s;
        int nt = 0;
        for (int d = 0; d < NDOM; d++) {
            int len = g_off[d + 1] - g_off[d];
            for (int m0 = 0; m0 < len; m0 += 128) {
                g_tile_d[nt] = d; g_tile_m[nt] = m0; nt++;
            }
        }
        g_ntiles = nt;
    }
    __syncthreads();
    for (int i = t; i < B_ROWS; i += blockDim.x) {
        int d = ind[i];
        int p = atomicAdd(&cur[d], 1);
        g_perm[p] = i;
    }
}

// ---------------- smem layout (floats) ----------------
// A fragments, MMA-permuted: [buf][split][mtile 0..7][lane 0..31][20]
#define AF_SZ (2 * 2 * 8 * 32 * 20)       // 20480 floats
// B tiles: [buf][split][k 0..31][BPAD], value = weff(k, n0+n)
#define BPAD 132
#define B_SZ (2 * 2 * 32 * BPAD)          // 16896 floats
#define SM_B       AF_SZ
#define SM_ROWIDX  (AF_SZ + B_SZ)
#define SM_BIAS    (SM_ROWIDX + 128)
#define GEMM_SMEM  ((SM_BIAS + 128) * 4)  // ~150.5 KB

__device__ __forceinline__ int af_off(int buf, int split, int mtile) {
    return ((buf * 2 + split) * 8 + mtile) * 640;   // 32*20
}
__device__ __forceinline__ int b_off(int buf, int split) {
    return SM_B + (buf * 2 + split) * (32 * BPAD);
}

// ---------------- 3xTF32 mma.sync grouped GEMM, fused weight build ----------
// Block tile M=128, N=128, K-chunk 32, double-buffered.
// 512 threads = 16 warps (4M x 4N), warp tile 32x32 -> 4 warps/SMSP.
template <int LAYER>
__global__ __launch_bounds__(THREADS, 1)
void gemm_mma(const float* __restrict__ xin, const float* __restrict__ sk,
              const float* __restrict__ dkk, const float* __restrict__ sb,
              const float* __restrict__ db, float* __restrict__ outp) {
    constexpr int K = (LAYER == 0) ? D0 : (LAYER == 1) ? D1 : D2;
    constexpr int N = (LAYER == 0) ? D1 : (LAYER == 1) ? D2 : D3;
    constexpr int NCH = K / 32;

    const int tyb = blockIdx.y;
    if (tyb >= g_ntiles) return;
    const int d   = g_tile_d[tyb];
    const int m0  = g_tile_m[tyb];
    const int off = g_off[d];
    const int len = g_off[d + 1] - off;
    const int n0  = blockIdx.x * 128;

    extern __shared__ float smf[];
    int*   rowIdx = (int*)(smf + SM_ROWIDX);
    float* biasS  = smf + SM_BIAS;

    const int tid  = threadIdx.x;
    const int lane = tid & 31;
    const int w    = tid >> 5;
    const int mw   = w >> 2;        // 0..3 -> M offset mw*32
    const int nw   = w & 3;         // 0..3 -> N offset nw*32
    const int grp  = lane >> 2;
    const int tig  = lane & 3;

    if (tid < 128) {
        int r = m0 + tid;
        int row = -1;
        if (r < len) row = (LAYER == 0) ? g_perm[off + r] : (off + r);
        rowIdx[tid] = row;
    }
    if (tid >= 128 && tid < 160) {
        int q = tid - 128;
        float4 a = *(const float4*)(sb + n0 + q * 4);
        float4 b = *(const float4*)(db + (size_t)d * N + n0 + q * 4);
        a.x += b.x; a.y += b.y; a.z += b.z; a.w += b.w;
        *(float4*)(biasS + q * 4) = a;
    }
    __syncthreads();

    const float* Ap  = (LAYER == 0) ? xin : (LAYER == 1) ? g_h1 : g_h2;
    float*       Cp  = (LAYER == 0) ? g_h1 : (LAYER == 1) ? g_h2 : outp;
    const float* dkd = dkk + (size_t)d * K * N;

    float acc[2][4][4];
#pragma unroll
    for (int i = 0; i < 2; i++)
#pragma unroll
        for (int j = 0; j < 4; j++)
#pragma unroll
            for (int q = 0; q < 4; q++) acc[i][j][q] = 0.f;

    // loader coords (2 items per thread):
    //   A: idx = tid + 512*i -> row = idx>>3 (0..127), fq8 = idx&7 (float4 col)
    //   W: idx = tid + 512*i -> k = idx>>5 (0..31), q = idx&31 (float4 col)
    const int arow0 = tid >> 3, afq = tid & 7;
    const int arow1 = (tid + THREADS) >> 3;
    const int wk0 = tid >> 5, wq = tid & 31;
    const int wk1 = (tid + THREADS) >> 5;
    int rws[2];
    rws[0] = rowIdx[arow0];
    rws[1] = rowIdx[arow1];

    float4 avA[2], avW[2];

#define LOADC(c)                                                              \
    {                                                                         \
        const int k0 = (c) * 32;                                              \
        _Pragma("unroll")                                                     \
        for (int i = 0; i < 2; i++) {                                         \
            int rr = rws[i];                                                  \
            avA[i] = (rr >= 0)                                                \
                ? *(const float4*)(Ap + (size_t)rr * K + k0 + afq * 4)        \
                : make_float4(0.f, 0.f, 0.f, 0.f);                            \
        }                                                                     \
        _Pragma("unroll")                                                     \
        for (int i = 0; i < 2; i++) {                                         \
            int kk = (i == 0) ? wk0 : wk1;                                    \
            int co = n0 + wq * 4;                                             \
            float4 s = *(const float4*)(sk  + (size_t)(k0 + kk) * N + co);    \
            float4 t = *(const float4*)(dkd + (size_t)(k0 + kk) * N + co);    \
            avW[i].x = s.x * t.x; avW[i].y = s.y * t.y;                       \
            avW[i].z = s.z * t.z; avW[i].w = s.w * t.w;                       \
        }                                                                     \
    }

#define STOREC(c)                                                             \
    {                                                                         \
        const int buf = (c) & 1;                                              \
        const int ks  = afq >> 1;                                             \
        const int kh2 = (afq & 1) * 2;                                        \
        _Pragma("unroll")                                                     \
        for (int i = 0; i < 2; i++) {                                         \
            int row = (i == 0) ? arow0 : arow1;                               \
            int mt  = row >> 4;                                               \
            int l0  = (row & 7) * 4;                                          \
            int ai  = ((row & 15) >= 8 ? 1 : 0) + kh2;                        \
            float* pb = smf + af_off(buf, 0, mt) + ks * 4 + ai;               \
            float* ps = smf + af_off(buf, 1, mt) + ks * 4 + ai;               \
            float4 v = avA[i];                                                \
            float bx = tf32r(v.x), by = tf32r(v.y);                           \
            float bz = tf32r(v.z), bw = tf32r(v.w);                           \
            pb[(l0 + 0) * 20] = bx; ps[(l0 + 0) * 20] = tf32r(v.x - bx);      \
            pb[(l0 + 1) * 20] = by; ps[(l0 + 1) * 20] = tf32r(v.y - by);      \
            pb[(l0 + 2) * 20] = bz; ps[(l0 + 2) * 20] = tf32r(v.z - bz);      \
            pb[(l0 + 3) * 20] = bw; ps[(l0 + 3) * 20] = tf32r(v.w - bw);      \
        }                                                                     \
        _Pragma("unroll")                                                     \
        for (int i = 0; i < 2; i++) {                                         \
            int kk = (i == 0) ? wk0 : wk1;                                    \
            float4 wv = avW[i];                                               \
            float4 wb, ws;                                                    \
            wb.x = tf32r(wv.x); ws.x = tf32r(wv.x - wb.x);                    \
            wb.y = tf32r(wv.y); ws.y = tf32r(wv.y - wb.y);                    \
            wb.z = tf32r(wv.z); ws.z = tf32r(wv.z - wb.z);                    \
            wb.w = tf32r(wv.w); ws.w = tf32r(wv.w - wb.w);                    \
            int o = kk * BPAD + wq * 4;                                       \
            *(float4*)(smf + b_off(buf, 0) + o) = wb;                         \
            *(float4*)(smf + b_off(buf, 1) + o) = ws;                         \
        }                                                                     \
    }

    LOADC(0);
    STOREC(0);

    for (int c = 0; c < NCH; c++) {
        const int buf = c & 1;
        __syncthreads();
        if (c + 1 < NCH) LOADC(c + 1);

        const float* afb = smf + af_off(buf, 0, mw * 2) + lane * 20;
        const float* afs = smf + af_off(buf, 1, mw * 2) + lane * 20;
        const float* bpb = smf + b_off(buf, 0);
        const float* bps = smf + b_off(buf, 1);
#pragma unroll
        for (int ks = 0; ks < 4; ks++) {
            const int kc = ks * 8 + tig;
            uint4 fab[2], fas[2];
#pragma unroll
            for (int mt = 0; mt < 2; mt++) {
                fab[mt] = *(const uint4*)(afb + mt * 640 + ks * 4);
                fas[mt] = *(const uint4*)(afs + mt * 640 + ks * 4);
            }
#pragma unroll
            for (int nt = 0; nt < 4; nt++) {
                int ncol = nw * 32 + nt * 8 + grp;
                uint32_t bb0 = __float_as_uint(bpb[kc * BPAD + ncol]);
                uint32_t bb1 = __float_as_uint(bpb[(kc + 4) * BPAD + ncol]);
                uint32_t bs0 = __float_as_uint(bps[kc * BPAD + ncol]);
                uint32_t bs1 = __float_as_uint(bps[(kc + 4) * BPAD + ncol]);
#pragma unroll
                for (int mt = 0; mt < 2; mt++) {
                    MMA_TF32(acc[mt][nt], fab[mt].x, fab[mt].y, fab[mt].z, fab[mt].w, bb0, bb1);
                    MMA_TF32(acc[mt][nt], fab[mt].x, fab[mt].y, fab[mt].z, fab[mt].w, bs0, bs1);
                    MMA_TF32(acc[mt][nt], fas[mt].x, fas[mt].y, fas[mt].z, fas[mt].w, bb0, bb1);
                }
            }
        }
        if (c + 1 < NCH) STOREC(c + 1);
    }

    // ---------------- epilogue: bias + relu + (scatter) store ----------------
#pragma unroll
    for (int mt = 0; mt < 2; mt++) {
#pragma unroll
        for (int half = 0; half < 2; half++) {
            int mrow = mw * 32 + mt * 16 + grp + half * 8;
            int r = m0 + mrow;
            if (r < len) {
                int orow = (LAYER == 2) ? g_perm[off + r] : (off + r);
                float* crow = Cp + (size_t)orow * N + n0;
#pragma unroll
                for (int nt = 0; nt < 4; nt++) {
                    int col = nw * 32 + nt * 8 + 2 * tig;
                    float2 o;
                    o.x = fmaxf(acc[mt][nt][half * 2 + 0] + biasS[col], 0.f);
                    o.y = fmaxf(acc[mt][nt][half * 2 + 1] + biasS[col + 1], 0.f);
                    *(float2*)(crow + col) = o;
                }
            }
        }
    }
}

// ---------------- launch ----------------
extern "C" void kernel_launch(void* const* d_in, const int* in_sizes, int n_in,
                              void* d_out, int out_size) {
    const float* x   = (const float*)d_in[0];
    const int*   ind = (const int*)  d_in[1];
    const float* sk0 = (const float*)d_in[2];
    const float* sb0 = (const float*)d_in[3];
    const float* dk0 = (const float*)d_in[4];
    const float* db0 = (const float*)d_in[5];
    const float* sk1 = (const float*)d_in[6];
    const float* sb1 = (const float*)d_in[7];
    const float* dk1 = (const float*)d_in[8];
    const float* db1 = (const float*)d_in[9];
    const float* sk2 = (const float*)d_in[10];
    const float* sb2 = (const float*)d_in[11];
    const float* dk2 = (const float*)d_in[12];
    const float* db2 = (const float*)d_in[13];
    float* out = (float*)d_out;

    cudaFuncSetAttribute(gemm_mma<0>, cudaFuncAttributeMaxDynamicSharedMemorySize, GEMM_SMEM);
    cudaFuncSetAttribute(gemm_mma<1>, cudaFuncAttributeMaxDynamicSharedMemorySize, GEMM_SMEM);
    cudaFuncSetAttribute(gemm_mma<2>, cudaFuncAttributeMaxDynamicSharedMemorySize, GEMM_SMEM);

    build_perm<<<1, 256>>>(ind);

    gemm_mma<0><<<dim3(D1 / 128, MAXTILES), THREADS, GEMM_SMEM>>>(x, sk0, dk0, sb0, db0, nullptr);
    gemm_mma<1><<<dim3(D2 / 128, MAXTILES), THREADS, GEMM_SMEM>>>(nullptr, sk1, dk1, sb1, db1, nullptr);
    gemm_mma<2><<<dim3(D3 / 128, MAXTILES), THREADS, GEMM_SMEM>>>(nullptr, sk2, dk2, sb2, db2, out);
}